// round 13
// baseline (speedup 1.0000x reference)
#include <cuda_runtime.h>
#include <cuda_fp16.h>
#include <cstdint>

#define Bsz 8
#define NSEQ 1024
#define OUTD 1024
#define DHD 128

#define DINLINE __device__ __forceinline__

// ---------------- scratch (allocation-free rule: __device__ globals) ----------
__device__ __align__(16) __half h_kv [8u*1024u*2048u];   // src_trans half [B*NS,2048]
__device__ __align__(16) __half h_q  [8u*1024u*1024u];   // tgt_trans half
__device__ __align__(16) __half h_upd[8u*1024u*1024u];   // tgt_update half
__device__ __align__(16) __half h_src[8u*1024u*1024u];   // fp16 inputs
__device__ __align__(16) __half h_tgt[8u*1024u*1024u];
__device__ __align__(16) __half h_ws [2u*1024u*1024u];
__device__ __align__(16) __half h_wt [1024u*1024u];
__device__ __align__(16) __half h_wo [2u*1024u*1024u];

// ---------------- helpers ------------------------------------------------------
DINLINE uint32_t smem_u32(const void* p) {
    uint32_t a;
    asm("{ .reg .u64 t; cvta.to.shared.u64 t, %1; cvt.u32.u64 %0, t; }" : "=r"(a) : "l"(p));
    return a;
}
DINLINE void cp16(uint32_t dst, const void* src) {
    asm volatile("cp.async.cg.shared.global [%0], [%1], 16;" :: "r"(dst), "l"(src) : "memory");
}
DINLINE void cp_commit() { asm volatile("cp.async.commit_group;" ::: "memory"); }
DINLINE void cp_wait0()  { asm volatile("cp.async.wait_group 0;" ::: "memory"); }
DINLINE void cp_wait1()  { asm volatile("cp.async.wait_group 1;" ::: "memory"); }
DINLINE void cp_wait2()  { asm volatile("cp.async.wait_group 2;" ::: "memory"); }

DINLINE void mma_h(float c[4], const uint32_t a[4], const uint32_t b[2]) {
    asm volatile(
        "mma.sync.aligned.m16n8k16.row.col.f32.f16.f16.f32 "
        "{%0,%1,%2,%3}, {%4,%5,%6,%7}, {%8,%9}, {%0,%1,%2,%3};"
        : "+f"(c[0]), "+f"(c[1]), "+f"(c[2]), "+f"(c[3])
        : "r"(a[0]), "r"(a[1]), "r"(a[2]), "r"(a[3]), "r"(b[0]), "r"(b[1]));
}

DINLINE void ldsm_x4(uint32_t& r0, uint32_t& r1, uint32_t& r2, uint32_t& r3, uint32_t a) {
    asm volatile("ldmatrix.sync.aligned.m8n8.x4.shared.b16 {%0,%1,%2,%3}, [%4];"
                 : "=r"(r0), "=r"(r1), "=r"(r2), "=r"(r3) : "r"(a));
}
DINLINE void ldsm_x4_t(uint32_t& r0, uint32_t& r1, uint32_t& r2, uint32_t& r3, uint32_t a) {
    asm volatile("ldmatrix.sync.aligned.m8n8.x4.trans.shared.b16 {%0,%1,%2,%3}, [%4];"
                 : "=r"(r0), "=r"(r1), "=r"(r2), "=r"(r3) : "r"(a));
}

DINLINE uint32_t ldh2(const __half* p) { return *(const uint32_t*)p; }
DINLINE uint32_t packh2(float x, float y) {
    __half2 h = __floats2half2_rn(x, y);
    return *reinterpret_cast<uint32_t*>(&h);
}

// ================================================================================
// fused f32 -> fp16 conversion (multi-segment, 16 floats/thread)
// ================================================================================
DINLINE void cvt8(const float4* in, uint4* out, int i) {
    float4 a = in[2 * i], b = in[2 * i + 1];
    uint4 o;
    o.x = packh2(a.x, a.y);
    o.y = packh2(a.z, a.w);
    o.z = packh2(b.x, b.y);
    o.w = packh2(b.z, b.w);
    out[i] = o;
}

// n0, n1, n2 must be even (uint4 counts)
__global__ void f2h_2(const float4* __restrict__ i0, uint4* __restrict__ o0, int n0,
                      const float4* __restrict__ i1, uint4* __restrict__ o1, int n1)
{
    int i = (blockIdx.x * blockDim.x + threadIdx.x) * 2;
    if (i < n0)            { cvt8(i0, o0, i); cvt8(i0, o0, i + 1); }
    else if (i - n0 < n1)  { int k = i - n0; cvt8(i1, o1, k); cvt8(i1, o1, k + 1); }
}

__global__ void f2h_3(const float4* __restrict__ i0, uint4* __restrict__ o0, int n0,
                      const float4* __restrict__ i1, uint4* __restrict__ o1, int n1,
                      const float4* __restrict__ i2, uint4* __restrict__ o2, int n2)
{
    int i = (blockIdx.x * blockDim.x + threadIdx.x) * 2;
    if (i < n0)                 { cvt8(i0, o0, i); cvt8(i0, o0, i + 1); }
    else if (i - n0 < n1)       { int k = i - n0; cvt8(i1, o1, k); cvt8(i1, o1, k + 1); }
    else if (i - n0 - n1 < n2)  { int k = i - n0 - n1; cvt8(i2, o2, k); cvt8(i2, o2, k + 1); }
}

// ================================================================================
// fp16 GEMM body (R10-proven): BM=BN=128, BK=32, 4 warps 64x64, ldmatrix.x4,
// 4-stage cp.async, single __syncthreads per k-block. outMode: 0=f32, 1=fp16,
// 2=f32 accumulate (+= existing C).
// ================================================================================
#define GS 4
#define STGH (2 * 128 * 40)
#define STGB (STGH * 2)

DINLINE void gemm_body(const __half* __restrict__ A0, const __half* __restrict__ A1,
                       const __half* __restrict__ W, int ldw,
                       const float* __restrict__ bias, const float* __restrict__ rowmask,
                       void* __restrict__ Cv, int ldc, int nkb, int outMode,
                       int mBase, int nBase, __half* smh)
{
    const uint32_t sb = smem_u32(smh);

    const int tid  = threadIdx.x;
    const int lane = tid & 31;
    const int wid  = tid >> 5;
    const int wm   = wid & 1;
    const int wn   = wid >> 1;
    const int g    = lane >> 2;
    const int tg   = lane & 3;

    uint32_t dOf[4];
    int aOf[4], wOf[4];
#pragma unroll
    for (int i = 0; i < 4; i++) {
        int idx = tid + i * 128;
        int row = idx >> 2, c = idx & 3;
        dOf[i] = row * 80 + c * 16;
        aOf[i] = (mBase + row) * 1024 + c * 8;
        wOf[i] = (nBase + row) * ldw + c * 8;
    }

    auto ISSUE = [&](int kb) {
        const int s = kb & 3;
        const int kg = kb * 32;
        const __half* Ap = (kg < 1024) ? A0 : A1;
        const int ka = kg & 1023;
        const uint32_t sa  = sb + s * STGB;
        const uint32_t sbb = sa + 128 * 80;
#pragma unroll
        for (int i = 0; i < 4; i++) cp16(sa  + dOf[i], Ap + aOf[i] + ka);
#pragma unroll
        for (int i = 0; i < 4; i++) cp16(sbb + dOf[i], W  + wOf[i] + kg);
        cp_commit();
    };

    const uint32_t aLn = (lane & 15) * 80 + ((lane & 16) ? 16u : 0u);
    const uint32_t bLn = (lane & 7) * 80 + ((lane & 16) ? 8u * 80u : 0u) + ((lane & 8) ? 16u : 0u);

    float acc[4][8][4];
#pragma unroll
    for (int mt = 0; mt < 4; mt++)
#pragma unroll
        for (int nt = 0; nt < 8; nt++)
#pragma unroll
            for (int i = 0; i < 4; i++) acc[mt][nt][i] = 0.f;

    ISSUE(0); ISSUE(1); ISSUE(2);

    for (int kb = 0; kb < nkb; kb++) {
        if (kb < nkb - 2)      cp_wait2();
        else if (kb < nkb - 1) cp_wait1();
        else                   cp_wait0();
        __syncthreads();
        if (kb + 3 < nkb) ISSUE(kb + 3);

        const uint32_t saA = sb + (kb & 3) * STGB;
        const uint32_t saB = saA + 128 * 80;
#pragma unroll
        for (int ks = 0; ks < 2; ks++) {
            const uint32_t aBase = saA + (uint32_t)(wm * 64) * 80 + ks * 32 + aLn;
            const uint32_t bBase = saB + (uint32_t)(wn * 64) * 80 + ks * 32 + bLn;
            uint32_t af[4][4], bf[8][2];
#pragma unroll
            for (int mt = 0; mt < 4; mt++)
                ldsm_x4(af[mt][0], af[mt][1], af[mt][2], af[mt][3], aBase + mt * 16 * 80);
#pragma unroll
            for (int p = 0; p < 4; p++)
                ldsm_x4(bf[2*p][0], bf[2*p][1], bf[2*p+1][0], bf[2*p+1][1], bBase + p * 16 * 80);
#pragma unroll
            for (int mt = 0; mt < 4; mt++)
#pragma unroll
                for (int nt = 0; nt < 8; nt++)
                    mma_h(acc[mt][nt], af[mt], bf[nt]);
        }
    }

#pragma unroll
    for (int mt = 0; mt < 4; mt++) {
        int r0 = mBase + wm * 64 + mt * 16 + g;
        float mk0 = rowmask ? rowmask[r0]     : 1.f;
        float mk1 = rowmask ? rowmask[r0 + 8] : 1.f;
#pragma unroll
        for (int nt = 0; nt < 8; nt++) {
            int c = nBase + wn * 64 + nt * 8 + 2 * tg;
            float b0 = bias ? bias[c]     : 0.f;
            float b1 = bias ? bias[c + 1] : 0.f;
            float v00 = (acc[mt][nt][0] + b0) * mk0;
            float v01 = (acc[mt][nt][1] + b1) * mk0;
            float v10 = (acc[mt][nt][2] + b0) * mk1;
            float v11 = (acc[mt][nt][3] + b1) * mk1;
            if (outMode == 1) {
                __half* Ch = (__half*)Cv;
                *(uint32_t*)(Ch + (size_t)r0 * ldc + c)       = packh2(v00, v01);
                *(uint32_t*)(Ch + (size_t)(r0 + 8) * ldc + c) = packh2(v10, v11);
            } else {
                float* Cf = (float*)Cv;
                float* p0 = Cf + (size_t)r0 * ldc + c;
                float* p1 = Cf + (size_t)(r0 + 8) * ldc + c;
                if (outMode == 2) {
                    float2 o0 = *(float2*)p0, o1 = *(float2*)p1;
                    v00 += o0.x; v01 += o0.y; v10 += o1.x; v11 += o1.y;
                }
                *(float2*)p0 = make_float2(v00, v01);
                *(float2*)p1 = make_float2(v10, v11);
            }
        }
    }
}

__global__ __launch_bounds__(128, 2)
void gemm_h(const __half* __restrict__ A0, const __half* __restrict__ A1,
            const __half* __restrict__ W, int ldw,
            const float* __restrict__ bias, const float* __restrict__ rowmask,
            void* __restrict__ Cv, int ldc, int nkb, int outMode)
{
    extern __shared__ __half smh[];
    gemm_body(A0, A1, W, ldw, bias, rowmask, Cv, ldc, nkb, outMode,
              blockIdx.y * 128, blockIdx.x * 128, smh);
}

// merged projection GEMMs: x<16 -> kv (N=2048), x>=16 -> q (N=1024)
__global__ __launch_bounds__(128, 2)
void gemm12_h(const __half* __restrict__ Asrc, const __half* __restrict__ Ws_,
              const float* __restrict__ bs_, const float* __restrict__ smask,
              __half* __restrict__ kv,
              const __half* __restrict__ Atgt, const __half* __restrict__ Wt_,
              const float* __restrict__ bt_, const float* __restrict__ tmask,
              __half* __restrict__ q)
{
    extern __shared__ __half smh[];
    if (blockIdx.x < 16)
        gemm_body(Asrc, Asrc, Ws_, 1024, bs_, smask, kv, 2048, 32, 1,
                  blockIdx.y * 128, blockIdx.x * 128, smh);
    else
        gemm_body(Atgt, Atgt, Wt_, 1024, bt_, tmask, q, 1024, 32, 1,
                  blockIdx.y * 128, (blockIdx.x - 16) * 128, smh);
}

// ================================================================================
// fp16 flash attention — VERBATIM R12 (proven): P in regs, Q in dedicated smem
// (ldmatrix per chunk), exp2 softmax, 2 CTAs/SM.
// smem (halves): Q[128][136] | K[2][64][136] | V[2][64][136] | f32 mask[2][64]
// ================================================================================
#define QH  (128 * 136)
#define KST (64 * 136)
#define VST (64 * 136)
#define KOFF QH
#define VOFF (QH + 2 * KST)
#define MBYTE ((VOFF + 2 * VST) * 2)
#define ATTN_SMEMB (MBYTE + 2 * 64 * 4)

__global__ __launch_bounds__(256, 2)
void attn_h(const __half* __restrict__ Q, const __half* __restrict__ KV,
            const float* __restrict__ smask, __half* __restrict__ O)
{
    extern __shared__ __half smh[];
    const uint32_t sb = smem_u32(smh);

    const int tid  = threadIdx.x;
    const int lane = tid & 31;
    const int w    = tid >> 5;
    const int g    = lane >> 2;
    const int tg   = lane & 3;

    const int bh = blockIdx.y;
    const int b  = bh >> 3;
    const int hh = bh & 7;
    const int t0 = blockIdx.x * 128;

    const __half* qg = Q + ((size_t)b * NSEQ + t0) * OUTD + hh * DHD;
    const __half* kg = KV + (size_t)b * NSEQ * (2 * OUTD) + hh * DHD;
    const __half* vg = kg + OUTD;
    const float*  mg = smask + (size_t)b * NSEQ;

    // ---- load Q (128 x 128 halves) into dedicated smem via cp.async ----
#pragma unroll
    for (int i = 0; i < 8; i++) {
        int idx = tid + i * 256;
        int row = idx >> 4, c8 = idx & 15;
        cp16(sb + (row * 136 + c8 * 8) * 2, qg + (size_t)row * OUTD + c8 * 8);
    }
    cp_commit();

    auto ISSUE = [&](int j) {
        const int st = j & 1;
#pragma unroll
        for (int i = 0; i < 4; i++) {
            int idx = tid + i * 256;
            int row = idx >> 4, c = idx & 15;
            size_t go = (size_t)(j * 64 + row) * (2 * OUTD) + c * 8;
            cp16(sb + (KOFF + st * KST + row * 136 + c * 8) * 2, kg + go);
            cp16(sb + (VOFF + st * VST + row * 136 + c * 8) * 2, vg + go);
        }
        if (tid < 16)
            cp16(sb + MBYTE + st * 256 + tid * 16, mg + j * 64 + tid * 4);
        cp_commit();
    };

    float oacc[16][4];
#pragma unroll
    for (int nt = 0; nt < 16; nt++)
#pragma unroll
        for (int i = 0; i < 4; i++) oacc[nt][i] = 0.f;
    float m0 = -1e30f, m1 = -1e30f, l0 = 0.f, l1 = 0.f;

    const float sc2 = 0.12756277212531545f;  // (1/sqrt(128)) * log2(e)
    const int vlane = (lane & 15) * 136 + ((lane & 16) ? 8 : 0);
    const uint32_t kLn = (lane & 7) * 272 + ((lane & 16) ? 8u * 272u : 0u) + ((lane & 8) ? 16u : 0u);
    const uint32_t qLn = (lane & 15) * 272 + ((lane & 16) ? 16u : 0u);
    const uint32_t qbase = sb + (uint32_t)(w * 16) * 272;

    ISSUE(0);

    for (int j = 0; j < NSEQ / 64; j++) {
        const int st = j & 1;
        cp_wait0();
        __syncthreads();
        if (j + 1 < NSEQ / 64) ISSUE(j + 1);

        const float*  msk = (const float*)((const char*)smh + MBYTE + st * 256);
        const uint32_t kbase = sb + (KOFF + st * KST) * 2;
        const uint32_t vbase = sb + (VOFF + st * VST) * 2;

        float sacc[8][4];
#pragma unroll
        for (int nt = 0; nt < 8; nt++)
#pragma unroll
            for (int i = 0; i < 4; i++) sacc[nt][i] = 0.f;

#pragma unroll
        for (int ks = 0; ks < 8; ks++) {
            uint32_t qa[4];
            ldsm_x4(qa[0], qa[1], qa[2], qa[3], qbase + ks * 32 + qLn);
            const uint32_t bBase = kbase + ks * 32 + kLn;
            uint32_t bf[8][2];
#pragma unroll
            for (int p = 0; p < 4; p++)
                ldsm_x4(bf[2*p][0], bf[2*p][1], bf[2*p+1][0], bf[2*p+1][1], bBase + p * 16 * 272);
#pragma unroll
            for (int nt = 0; nt < 8; nt++)
                mma_h(sacc[nt], qa, bf[nt]);
        }

        float rmax0 = -1e30f, rmax1 = -1e30f;
#pragma unroll
        for (int nt = 0; nt < 8; nt++) {
#pragma unroll
            for (int i = 0; i < 4; i++) {
                float sv = sacc[nt][i] * sc2;
                int col = nt * 8 + 2 * tg + (i & 1);
                if (msk[col] == 0.f) sv = -1e30f;
                sacc[nt][i] = sv;
                if (i < 2) rmax0 = fmaxf(rmax0, sv);
                else       rmax1 = fmaxf(rmax1, sv);
            }
        }
        rmax0 = fmaxf(rmax0, __shfl_xor_sync(0xffffffffu, rmax0, 1));
        rmax0 = fmaxf(rmax0, __shfl_xor_sync(0xffffffffu, rmax0, 2));
        rmax1 = fmaxf(rmax1, __shfl_xor_sync(0xffffffffu, rmax1, 1));
        rmax1 = fmaxf(rmax1, __shfl_xor_sync(0xffffffffu, rmax1, 2));

        float mn0 = fmaxf(m0, rmax0), mn1 = fmaxf(m1, rmax1);
        float cf0 = exp2f(m0 - mn0), cf1 = exp2f(m1 - mn1);
        m0 = mn0; m1 = mn1;

        uint32_t pp[8][2];
        float rs0 = 0.f, rs1 = 0.f;
#pragma unroll
        for (int nt = 0; nt < 8; nt++) {
            float p0 = exp2f(sacc[nt][0] - mn0);
            float p1 = exp2f(sacc[nt][1] - mn0);
            float p2 = exp2f(sacc[nt][2] - mn1);
            float p3 = exp2f(sacc[nt][3] - mn1);
            rs0 += p0 + p1; rs1 += p2 + p3;
            pp[nt][0] = packh2(p0, p1);
            pp[nt][1] = packh2(p2, p3);
        }
        rs0 += __shfl_xor_sync(0xffffffffu, rs0, 1);
        rs0 += __shfl_xor_sync(0xffffffffu, rs0, 2);
        rs1 += __shfl_xor_sync(0xffffffffu, rs1, 1);
        rs1 += __shfl_xor_sync(0xffffffffu, rs1, 2);
        l0 = l0 * cf0 + rs0;
        l1 = l1 * cf1 + rs1;

#pragma unroll
        for (int nt = 0; nt < 16; nt++) {
            oacc[nt][0] *= cf0; oacc[nt][1] *= cf0;
            oacc[nt][2] *= cf1; oacc[nt][3] *= cf1;
        }

#pragma unroll
        for (int ks = 0; ks < 4; ks++) {
            uint32_t pa[4];
            pa[0] = pp[2 * ks][0];
            pa[1] = pp[2 * ks][1];
            pa[2] = pp[2 * ks + 1][0];
            pa[3] = pp[2 * ks + 1][1];
            const uint32_t vrow = vbase + (ks * 16 * 136 + vlane) * 2;
#pragma unroll
            for (int dg = 0; dg < 8; dg++) {
                uint32_t r0, r1, r2, r3;
                ldsm_x4_t(r0, r1, r2, r3, vrow + dg * 32);
                uint32_t b0[2] = {r0, r1}, b1[2] = {r2, r3};
                mma_h(oacc[2 * dg],     pa, b0);
                mma_h(oacc[2 * dg + 1], pa, b1);
            }
        }
    }

    float inv0 = 1.f / l0, inv1 = 1.f / l1;
    const int tr0 = t0 + w * 16 + g;
    __half* og = O + (size_t)b * NSEQ * OUTD + hh * DHD;
#pragma unroll
    for (int nt = 0; nt < 16; nt++) {
        int dc = nt * 8 + 2 * tg;
        *(uint32_t*)(og + (size_t)tr0 * OUTD + dc) =
            packh2(oacc[nt][0] * inv0, oacc[nt][1] * inv0);
        *(uint32_t*)(og + (size_t)(tr0 + 8) * OUTD + dc) =
            packh2(oacc[nt][2] * inv1, oacc[nt][3] * inv1);
    }
}

// ================================================================================
// launch — fork gemm4a (tgt@Wo1+bo) onto a side stream, concurrent with
// gemm12 + attention; join before gemm4b (+= upd@Wo2).
// ================================================================================
extern "C" void kernel_launch(void* const* d_in, const int* in_sizes, int n_in,
                              void* d_out, int out_size)
{
    const float* src      = (const float*)d_in[0];
    const float* tgt      = (const float*)d_in[1];
    const float* src_mask = (const float*)d_in[2];
    const float* tgt_mask = (const float*)d_in[3];
    const float* Ws       = (const float*)d_in[4];
    const float* bs       = (const float*)d_in[5];
    const float* Wt       = (const float*)d_in[6];
    const float* bt       = (const float*)d_in[7];
    const float* Wo       = (const float*)d_in[8];
    const float* bo       = (const float*)d_in[9];
    float* out = (float*)d_out;

    __half *kv, *q, *upd, *hsrc, *htgt, *hws, *hwt, *hwo;
    cudaGetSymbolAddress((void**)&kv,   h_kv);
    cudaGetSymbolAddress((void**)&q,    h_q);
    cudaGetSymbolAddress((void**)&upd,  h_upd);
    cudaGetSymbolAddress((void**)&hsrc, h_src);
    cudaGetSymbolAddress((void**)&htgt, h_tgt);
    cudaGetSymbolAddress((void**)&hws,  h_ws);
    cudaGetSymbolAddress((void**)&hwt,  h_wt);
    cudaGetSymbolAddress((void**)&hwo,  h_wo);

    const int gSmem = GS * STGB;               // 81920
    const int aSmem = ATTN_SMEMB;              // ~105KB
    cudaFuncSetAttribute(gemm_h,   cudaFuncAttributeMaxDynamicSharedMemorySize, gSmem);
    cudaFuncSetAttribute(gemm12_h, cudaFuncAttributeMaxDynamicSharedMemorySize, gSmem);
    cudaFuncSetAttribute(attn_h,   cudaFuncAttributeMaxDynamicSharedMemorySize, aSmem);

    // side stream + fork/join events (created fresh; kernel_launch is called only
    // a handful of times, handles intentionally not destroyed — no device memory)
    cudaStream_t s2;
    cudaEvent_t evFork, evJoin;
    cudaStreamCreateWithFlags(&s2, cudaStreamNonBlocking);
    cudaEventCreateWithFlags(&evFork, cudaEventDisableTiming);
    cudaEventCreateWithFlags(&evJoin, cudaEventDisableTiming);

    // 0) fused f32 -> fp16 conversions
    const int nSrc = 8*1024*1024/8, nW2 = 2*1024*1024/8, nW1 = 1024*1024/8;
    f2h_2<<<(2*nSrc/2 + 255) / 256, 256>>>(
        (const float4*)src, (uint4*)hsrc, nSrc,
        (const float4*)tgt, (uint4*)htgt, nSrc);
    f2h_3<<<((2*nW2 + nW1)/2 + 255) / 256, 256>>>(
        (const float4*)Ws, (uint4*)hws, nW2,
        (const float4*)Wt, (uint4*)hwt, nW1,
        (const float4*)Wo, (uint4*)hwo, nW2);

    const int M = Bsz * NSEQ; // 8192

    // fork: gemm4a (out = tgt @ Wo1^T + bo) runs concurrently on s2
    cudaEventRecord(evFork, 0);
    cudaStreamWaitEvent(s2, evFork, 0);
    gemm_h<<<dim3(1024 / 128, M / 128), 128, gSmem, s2>>>(
        htgt, htgt, hwo, 2048, bo, nullptr, out, 1024, 32, 0);
    cudaEventRecord(evJoin, s2);

    // main stream: projections + attention
    gemm12_h<<<dim3(24, M / 128), 128, gSmem>>>(
        hsrc, hws, bs, src_mask, kv,
        htgt, hwt, bt, tgt_mask, q);

    attn_h<<<dim3(NSEQ / 128, Bsz * 8), 256, aSmem>>>(q, kv, src_mask, upd);

    // join, then gemm4b: out += upd @ Wo2^T
    cudaStreamWaitEvent(0, evJoin, 0);
    gemm_h<<<dim3(1024 / 128, M / 128), 128, gSmem>>>(
        upd, upd, hwo + 1024, 2048, nullptr, nullptr, out, 1024, 32, 2);
}

// round 14
// speedup vs baseline: 1.0343x; 1.0343x over previous
#include <cuda_runtime.h>
#include <cuda_fp16.h>
#include <cstdint>

#define Bsz 8
#define NSEQ 1024
#define OUTD 1024
#define DHD 128

#define DINLINE __device__ __forceinline__

// ---------------- scratch (allocation-free rule: __device__ globals) ----------
__device__ __align__(16) __half h_kv [8u*1024u*2048u];   // src_trans half [B*NS,2048]
__device__ __align__(16) __half h_q  [8u*1024u*1024u];   // tgt_trans half
__device__ __align__(16) __half h_upd[8u*1024u*1024u];   // tgt_update half
__device__ __align__(16) __half h_src[8u*1024u*1024u];   // fp16 inputs
__device__ __align__(16) __half h_tgt[8u*1024u*1024u];
__device__ __align__(16) __half h_ws [2u*1024u*1024u];
__device__ __align__(16) __half h_wt [1024u*1024u];
__device__ __align__(16) __half h_wo [2u*1024u*1024u];

// ---------------- helpers ------------------------------------------------------
DINLINE uint32_t smem_u32(const void* p) {
    uint32_t a;
    asm("{ .reg .u64 t; cvta.to.shared.u64 t, %1; cvt.u32.u64 %0, t; }" : "=r"(a) : "l"(p));
    return a;
}
DINLINE void cp16(uint32_t dst, const void* src) {
    asm volatile("cp.async.cg.shared.global [%0], [%1], 16;" :: "r"(dst), "l"(src) : "memory");
}
DINLINE void cp_commit() { asm volatile("cp.async.commit_group;" ::: "memory"); }
DINLINE void cp_wait0()  { asm volatile("cp.async.wait_group 0;" ::: "memory"); }
DINLINE void cp_wait1()  { asm volatile("cp.async.wait_group 1;" ::: "memory"); }
DINLINE void cp_wait2()  { asm volatile("cp.async.wait_group 2;" ::: "memory"); }

DINLINE void mma_h(float c[4], const uint32_t a[4], const uint32_t b[2]) {
    asm volatile(
        "mma.sync.aligned.m16n8k16.row.col.f32.f16.f16.f32 "
        "{%0,%1,%2,%3}, {%4,%5,%6,%7}, {%8,%9}, {%0,%1,%2,%3};"
        : "+f"(c[0]), "+f"(c[1]), "+f"(c[2]), "+f"(c[3])
        : "r"(a[0]), "r"(a[1]), "r"(a[2]), "r"(a[3]), "r"(b[0]), "r"(b[1]));
}

DINLINE void ldsm_x4(uint32_t& r0, uint32_t& r1, uint32_t& r2, uint32_t& r3, uint32_t a) {
    asm volatile("ldmatrix.sync.aligned.m8n8.x4.shared.b16 {%0,%1,%2,%3}, [%4];"
                 : "=r"(r0), "=r"(r1), "=r"(r2), "=r"(r3) : "r"(a));
}
DINLINE void ldsm_x4_t(uint32_t& r0, uint32_t& r1, uint32_t& r2, uint32_t& r3, uint32_t a) {
    asm volatile("ldmatrix.sync.aligned.m8n8.x4.trans.shared.b16 {%0,%1,%2,%3}, [%4];"
                 : "=r"(r0), "=r"(r1), "=r"(r2), "=r"(r3) : "r"(a));
}

DINLINE uint32_t ldh2(const __half* p) { return *(const uint32_t*)p; }
DINLINE uint32_t packh2(float x, float y) {
    __half2 h = __floats2half2_rn(x, y);
    return *reinterpret_cast<uint32_t*>(&h);
}

// ================================================================================
// fused f32 -> fp16 conversion (multi-segment, 16 floats/thread)
// ================================================================================
DINLINE void cvt8(const float4* in, uint4* out, int i) {
    float4 a = in[2 * i], b = in[2 * i + 1];
    uint4 o;
    o.x = packh2(a.x, a.y);
    o.y = packh2(a.z, a.w);
    o.z = packh2(b.x, b.y);
    o.w = packh2(b.z, b.w);
    out[i] = o;
}

// n0, n1, n2 are uint4 counts (all even here)
__global__ void f2h_2(const float4* __restrict__ i0, uint4* __restrict__ o0, int n0,
                      const float4* __restrict__ i1, uint4* __restrict__ o1, int n1)
{
    int i = (blockIdx.x * blockDim.x + threadIdx.x) * 2;
    if (i < n0)            { cvt8(i0, o0, i); cvt8(i0, o0, i + 1); }
    else if (i - n0 < n1)  { int k = i - n0; cvt8(i1, o1, k); cvt8(i1, o1, k + 1); }
}

__global__ void f2h_3(const float4* __restrict__ i0, uint4* __restrict__ o0, int n0,
                      const float4* __restrict__ i1, uint4* __restrict__ o1, int n1,
                      const float4* __restrict__ i2, uint4* __restrict__ o2, int n2)
{
    int i = (blockIdx.x * blockDim.x + threadIdx.x) * 2;
    if (i < n0)                 { cvt8(i0, o0, i); cvt8(i0, o0, i + 1); }
    else if (i - n0 < n1)       { int k = i - n0; cvt8(i1, o1, k); cvt8(i1, o1, k + 1); }
    else if (i - n0 - n1 < n2)  { int k = i - n0 - n1; cvt8(i2, o2, k); cvt8(i2, o2, k + 1); }
}

// ================================================================================
// fp16 GEMM body (R10-proven): BM=BN=128, BK=32, 4 warps 64x64, ldmatrix.x4,
// 4-stage cp.async, single __syncthreads per k-block. outHalf: 1=fp16, 0=f32.
// ================================================================================
#define GS 4
#define STGH (2 * 128 * 40)
#define STGB (STGH * 2)

DINLINE void gemm_body(const __half* __restrict__ A0, const __half* __restrict__ A1,
                       const __half* __restrict__ W, int ldw,
                       const float* __restrict__ bias, const float* __restrict__ rowmask,
                       void* __restrict__ Cv, int ldc, int nkb, int outHalf,
                       int mBase, int nBase, __half* smh)
{
    const uint32_t sb = smem_u32(smh);

    const int tid  = threadIdx.x;
    const int lane = tid & 31;
    const int wid  = tid >> 5;
    const int wm   = wid & 1;
    const int wn   = wid >> 1;
    const int g    = lane >> 2;
    const int tg   = lane & 3;

    uint32_t dOf[4];
    int aOf[4], wOf[4];
#pragma unroll
    for (int i = 0; i < 4; i++) {
        int idx = tid + i * 128;
        int row = idx >> 2, c = idx & 3;
        dOf[i] = row * 80 + c * 16;
        aOf[i] = (mBase + row) * 1024 + c * 8;
        wOf[i] = (nBase + row) * ldw + c * 8;
    }

    auto ISSUE = [&](int kb) {
        const int s = kb & 3;
        const int kg = kb * 32;
        const __half* Ap = (kg < 1024) ? A0 : A1;
        const int ka = kg & 1023;
        const uint32_t sa  = sb + s * STGB;
        const uint32_t sbb = sa + 128 * 80;
#pragma unroll
        for (int i = 0; i < 4; i++) cp16(sa  + dOf[i], Ap + aOf[i] + ka);
#pragma unroll
        for (int i = 0; i < 4; i++) cp16(sbb + dOf[i], W  + wOf[i] + kg);
        cp_commit();
    };

    const uint32_t aLn = (lane & 15) * 80 + ((lane & 16) ? 16u : 0u);
    const uint32_t bLn = (lane & 7) * 80 + ((lane & 16) ? 8u * 80u : 0u) + ((lane & 8) ? 16u : 0u);

    float acc[4][8][4];
#pragma unroll
    for (int mt = 0; mt < 4; mt++)
#pragma unroll
        for (int nt = 0; nt < 8; nt++)
#pragma unroll
            for (int i = 0; i < 4; i++) acc[mt][nt][i] = 0.f;

    ISSUE(0); ISSUE(1); ISSUE(2);

    for (int kb = 0; kb < nkb; kb++) {
        if (kb < nkb - 2)      cp_wait2();
        else if (kb < nkb - 1) cp_wait1();
        else                   cp_wait0();
        __syncthreads();
        if (kb + 3 < nkb) ISSUE(kb + 3);

        const uint32_t saA = sb + (kb & 3) * STGB;
        const uint32_t saB = saA + 128 * 80;
#pragma unroll
        for (int ks = 0; ks < 2; ks++) {
            const uint32_t aBase = saA + (uint32_t)(wm * 64) * 80 + ks * 32 + aLn;
            const uint32_t bBase = saB + (uint32_t)(wn * 64) * 80 + ks * 32 + bLn;
            uint32_t af[4][4], bf[8][2];
#pragma unroll
            for (int mt = 0; mt < 4; mt++)
                ldsm_x4(af[mt][0], af[mt][1], af[mt][2], af[mt][3], aBase + mt * 16 * 80);
#pragma unroll
            for (int p = 0; p < 4; p++)
                ldsm_x4(bf[2*p][0], bf[2*p][1], bf[2*p+1][0], bf[2*p+1][1], bBase + p * 16 * 80);
#pragma unroll
            for (int mt = 0; mt < 4; mt++)
#pragma unroll
                for (int nt = 0; nt < 8; nt++)
                    mma_h(acc[mt][nt], af[mt], bf[nt]);
        }
    }

#pragma unroll
    for (int mt = 0; mt < 4; mt++) {
        int r0 = mBase + wm * 64 + mt * 16 + g;
        float mk0 = rowmask ? rowmask[r0]     : 1.f;
        float mk1 = rowmask ? rowmask[r0 + 8] : 1.f;
#pragma unroll
        for (int nt = 0; nt < 8; nt++) {
            int c = nBase + wn * 64 + nt * 8 + 2 * tg;
            float b0 = bias ? bias[c]     : 0.f;
            float b1 = bias ? bias[c + 1] : 0.f;
            float v00 = (acc[mt][nt][0] + b0) * mk0;
            float v01 = (acc[mt][nt][1] + b1) * mk0;
            float v10 = (acc[mt][nt][2] + b0) * mk1;
            float v11 = (acc[mt][nt][3] + b1) * mk1;
            if (outHalf) {
                __half* Ch = (__half*)Cv;
                *(uint32_t*)(Ch + (size_t)r0 * ldc + c)       = packh2(v00, v01);
                *(uint32_t*)(Ch + (size_t)(r0 + 8) * ldc + c) = packh2(v10, v11);
            } else {
                float* Cf = (float*)Cv;
                *(float2*)(Cf + (size_t)r0 * ldc + c)       = make_float2(v00, v01);
                *(float2*)(Cf + (size_t)(r0 + 8) * ldc + c) = make_float2(v10, v11);
            }
        }
    }
}

// out-GEMM (fused K=2048 concat)
__global__ __launch_bounds__(128, 2)
void gemm_h(const __half* __restrict__ A0, const __half* __restrict__ A1,
            const __half* __restrict__ W, int ldw,
            const float* __restrict__ bias, const float* __restrict__ rowmask,
            void* __restrict__ Cv, int ldc, int nkb, int outHalf)
{
    extern __shared__ __half smh[];
    gemm_body(A0, A1, W, ldw, bias, rowmask, Cv, ldc, nkb, outHalf,
              blockIdx.y * 128, blockIdx.x * 128, smh);
}

// merged projection GEMMs: x<16 -> kv (N=2048), x>=16 -> q (N=1024)
__global__ __launch_bounds__(128, 2)
void gemm12_h(const __half* __restrict__ Asrc, const __half* __restrict__ Ws_,
              const float* __restrict__ bs_, const float* __restrict__ smask,
              __half* __restrict__ kv,
              const __half* __restrict__ Atgt, const __half* __restrict__ Wt_,
              const float* __restrict__ bt_, const float* __restrict__ tmask,
              __half* __restrict__ q)
{
    extern __shared__ __half smh[];
    if (blockIdx.x < 16)
        gemm_body(Asrc, Asrc, Ws_, 1024, bs_, smask, kv, 2048, 32, 1,
                  blockIdx.y * 128, blockIdx.x * 128, smh);
    else
        gemm_body(Atgt, Atgt, Wt_, 1024, bt_, tmask, q, 1024, 32, 1,
                  blockIdx.y * 128, (blockIdx.x - 16) * 128, smh);
}

// ================================================================================
// fp16 flash attention — VERBATIM R12 (proven): P in regs, Q in dedicated smem
// (ldmatrix per chunk), exp2 softmax, 2 CTAs/SM.
// smem (halves): Q[128][136] | K[2][64][136] | V[2][64][136] | f32 mask[2][64]
// ================================================================================
#define QH  (128 * 136)
#define KST (64 * 136)
#define VST (64 * 136)
#define KOFF QH
#define VOFF (QH + 2 * KST)
#define MBYTE ((VOFF + 2 * VST) * 2)
#define ATTN_SMEMB (MBYTE + 2 * 64 * 4)

__global__ __launch_bounds__(256, 2)
void attn_h(const __half* __restrict__ Q, const __half* __restrict__ KV,
            const float* __restrict__ smask, __half* __restrict__ O)
{
    extern __shared__ __half smh[];
    const uint32_t sb = smem_u32(smh);

    const int tid  = threadIdx.x;
    const int lane = tid & 31;
    const int w    = tid >> 5;
    const int g    = lane >> 2;
    const int tg   = lane & 3;

    const int bh = blockIdx.y;
    const int b  = bh >> 3;
    const int hh = bh & 7;
    const int t0 = blockIdx.x * 128;

    const __half* qg = Q + ((size_t)b * NSEQ + t0) * OUTD + hh * DHD;
    const __half* kg = KV + (size_t)b * NSEQ * (2 * OUTD) + hh * DHD;
    const __half* vg = kg + OUTD;
    const float*  mg = smask + (size_t)b * NSEQ;

    // ---- load Q (128 x 128 halves) into dedicated smem via cp.async ----
#pragma unroll
    for (int i = 0; i < 8; i++) {
        int idx = tid + i * 256;
        int row = idx >> 4, c8 = idx & 15;
        cp16(sb + (row * 136 + c8 * 8) * 2, qg + (size_t)row * OUTD + c8 * 8);
    }
    cp_commit();

    auto ISSUE = [&](int j) {
        const int st = j & 1;
#pragma unroll
        for (int i = 0; i < 4; i++) {
            int idx = tid + i * 256;
            int row = idx >> 4, c = idx & 15;
            size_t go = (size_t)(j * 64 + row) * (2 * OUTD) + c * 8;
            cp16(sb + (KOFF + st * KST + row * 136 + c * 8) * 2, kg + go);
            cp16(sb + (VOFF + st * VST + row * 136 + c * 8) * 2, vg + go);
        }
        if (tid < 16)
            cp16(sb + MBYTE + st * 256 + tid * 16, mg + j * 64 + tid * 4);
        cp_commit();
    };

    float oacc[16][4];
#pragma unroll
    for (int nt = 0; nt < 16; nt++)
#pragma unroll
        for (int i = 0; i < 4; i++) oacc[nt][i] = 0.f;
    float m0 = -1e30f, m1 = -1e30f, l0 = 0.f, l1 = 0.f;

    const float sc2 = 0.12756277212531545f;  // (1/sqrt(128)) * log2(e)
    const int vlane = (lane & 15) * 136 + ((lane & 16) ? 8 : 0);
    const uint32_t kLn = (lane & 7) * 272 + ((lane & 16) ? 8u * 272u : 0u) + ((lane & 8) ? 16u : 0u);
    const uint32_t qLn = (lane & 15) * 272 + ((lane & 16) ? 16u : 0u);
    const uint32_t qbase = sb + (uint32_t)(w * 16) * 272;

    ISSUE(0);

    for (int j = 0; j < NSEQ / 64; j++) {
        const int st = j & 1;
        cp_wait0();
        __syncthreads();
        if (j + 1 < NSEQ / 64) ISSUE(j + 1);

        const float*  msk = (const float*)((const char*)smh + MBYTE + st * 256);
        const uint32_t kbase = sb + (KOFF + st * KST) * 2;
        const uint32_t vbase = sb + (VOFF + st * VST) * 2;

        float sacc[8][4];
#pragma unroll
        for (int nt = 0; nt < 8; nt++)
#pragma unroll
            for (int i = 0; i < 4; i++) sacc[nt][i] = 0.f;

#pragma unroll
        for (int ks = 0; ks < 8; ks++) {
            uint32_t qa[4];
            ldsm_x4(qa[0], qa[1], qa[2], qa[3], qbase + ks * 32 + qLn);
            const uint32_t bBase = kbase + ks * 32 + kLn;
            uint32_t bf[8][2];
#pragma unroll
            for (int p = 0; p < 4; p++)
                ldsm_x4(bf[2*p][0], bf[2*p][1], bf[2*p+1][0], bf[2*p+1][1], bBase + p * 16 * 272);
#pragma unroll
            for (int nt = 0; nt < 8; nt++)
                mma_h(sacc[nt], qa, bf[nt]);
        }

        float rmax0 = -1e30f, rmax1 = -1e30f;
#pragma unroll
        for (int nt = 0; nt < 8; nt++) {
#pragma unroll
            for (int i = 0; i < 4; i++) {
                float sv = sacc[nt][i] * sc2;
                int col = nt * 8 + 2 * tg + (i & 1);
                if (msk[col] == 0.f) sv = -1e30f;
                sacc[nt][i] = sv;
                if (i < 2) rmax0 = fmaxf(rmax0, sv);
                else       rmax1 = fmaxf(rmax1, sv);
            }
        }
        rmax0 = fmaxf(rmax0, __shfl_xor_sync(0xffffffffu, rmax0, 1));
        rmax0 = fmaxf(rmax0, __shfl_xor_sync(0xffffffffu, rmax0, 2));
        rmax1 = fmaxf(rmax1, __shfl_xor_sync(0xffffffffu, rmax1, 1));
        rmax1 = fmaxf(rmax1, __shfl_xor_sync(0xffffffffu, rmax1, 2));

        float mn0 = fmaxf(m0, rmax0), mn1 = fmaxf(m1, rmax1);
        float cf0 = exp2f(m0 - mn0), cf1 = exp2f(m1 - mn1);
        m0 = mn0; m1 = mn1;

        uint32_t pp[8][2];
        float rs0 = 0.f, rs1 = 0.f;
#pragma unroll
        for (int nt = 0; nt < 8; nt++) {
            float p0 = exp2f(sacc[nt][0] - mn0);
            float p1 = exp2f(sacc[nt][1] - mn0);
            float p2 = exp2f(sacc[nt][2] - mn1);
            float p3 = exp2f(sacc[nt][3] - mn1);
            rs0 += p0 + p1; rs1 += p2 + p3;
            pp[nt][0] = packh2(p0, p1);
            pp[nt][1] = packh2(p2, p3);
        }
        rs0 += __shfl_xor_sync(0xffffffffu, rs0, 1);
        rs0 += __shfl_xor_sync(0xffffffffu, rs0, 2);
        rs1 += __shfl_xor_sync(0xffffffffu, rs1, 1);
        rs1 += __shfl_xor_sync(0xffffffffu, rs1, 2);
        l0 = l0 * cf0 + rs0;
        l1 = l1 * cf1 + rs1;

#pragma unroll
        for (int nt = 0; nt < 16; nt++) {
            oacc[nt][0] *= cf0; oacc[nt][1] *= cf0;
            oacc[nt][2] *= cf1; oacc[nt][3] *= cf1;
        }

#pragma unroll
        for (int ks = 0; ks < 4; ks++) {
            uint32_t pa[4];
            pa[0] = pp[2 * ks][0];
            pa[1] = pp[2 * ks][1];
            pa[2] = pp[2 * ks + 1][0];
            pa[3] = pp[2 * ks + 1][1];
            const uint32_t vrow = vbase + (ks * 16 * 136 + vlane) * 2;
#pragma unroll
            for (int dg = 0; dg < 8; dg++) {
                uint32_t r0, r1, r2, r3;
                ldsm_x4_t(r0, r1, r2, r3, vrow + dg * 32);
                uint32_t b0[2] = {r0, r1}, b1[2] = {r2, r3};
                mma_h(oacc[2 * dg],     pa, b0);
                mma_h(oacc[2 * dg + 1], pa, b1);
            }
        }
    }

    float inv0 = 1.f / l0, inv1 = 1.f / l1;
    const int tr0 = t0 + w * 16 + g;
    __half* og = O + (size_t)b * NSEQ * OUTD + hh * DHD;
#pragma unroll
    for (int nt = 0; nt < 16; nt++) {
        int dc = nt * 8 + 2 * tg;
        *(uint32_t*)(og + (size_t)tr0 * OUTD + dc) =
            packh2(oacc[nt][0] * inv0, oacc[nt][1] * inv0);
        *(uint32_t*)(og + (size_t)(tr0 + 8) * OUTD + dc) =
            packh2(oacc[nt][2] * inv1, oacc[nt][3] * inv1);
    }
}

// ================================================================================
// launch — R12 structure restored (single stream, fused out-GEMM)
// ================================================================================
extern "C" void kernel_launch(void* const* d_in, const int* in_sizes, int n_in,
                              void* d_out, int out_size)
{
    const float* src      = (const float*)d_in[0];
    const float* tgt      = (const float*)d_in[1];
    const float* src_mask = (const float*)d_in[2];
    const float* tgt_mask = (const float*)d_in[3];
    const float* Ws       = (const float*)d_in[4];
    const float* bs       = (const float*)d_in[5];
    const float* Wt       = (const float*)d_in[6];
    const float* bt       = (const float*)d_in[7];
    const float* Wo       = (const float*)d_in[8];
    const float* bo       = (const float*)d_in[9];
    float* out = (float*)d_out;

    __half *kv, *q, *upd, *hsrc, *htgt, *hws, *hwt, *hwo;
    cudaGetSymbolAddress((void**)&kv,   h_kv);
    cudaGetSymbolAddress((void**)&q,    h_q);
    cudaGetSymbolAddress((void**)&upd,  h_upd);
    cudaGetSymbolAddress((void**)&hsrc, h_src);
    cudaGetSymbolAddress((void**)&htgt, h_tgt);
    cudaGetSymbolAddress((void**)&hws,  h_ws);
    cudaGetSymbolAddress((void**)&hwt,  h_wt);
    cudaGetSymbolAddress((void**)&hwo,  h_wo);

    const int gSmem = GS * STGB;               // 81920
    const int aSmem = ATTN_SMEMB;              // ~105KB
    cudaFuncSetAttribute(gemm_h,   cudaFuncAttributeMaxDynamicSharedMemorySize, gSmem);
    cudaFuncSetAttribute(gemm12_h, cudaFuncAttributeMaxDynamicSharedMemorySize, gSmem);
    cudaFuncSetAttribute(attn_h,   cudaFuncAttributeMaxDynamicSharedMemorySize, aSmem);

    // 0) fused f32 -> fp16 conversions (2 launches, 16 floats/thread)
    const int nSrc = 8*1024*1024/8, nW2 = 2*1024*1024/8, nW1 = 1024*1024/8;
    f2h_2<<<(2*nSrc/2 + 255) / 256, 256>>>(
        (const float4*)src, (uint4*)hsrc, nSrc,
        (const float4*)tgt, (uint4*)htgt, nSrc);
    f2h_3<<<((2*nW2 + nW1)/2 + 255) / 256, 256>>>(
        (const float4*)Ws, (uint4*)hws, nW2,
        (const float4*)Wt, (uint4*)hwt, nW1,
        (const float4*)Wo, (uint4*)hwo, nW2);

    const int M = Bsz * NSEQ; // 8192

    // 1+2) merged: kv = src@Ws^T+bs (*src_mask), q = tgt@Wt^T+bt (*tgt_mask)
    gemm12_h<<<dim3(24, M / 128), 128, gSmem>>>(
        hsrc, hws, bs, src_mask, kv,
        htgt, hwt, bt, tgt_mask, q);

    // 3) flash attention -> upd fp16       [8192, 1024]
    attn_h<<<dim3(NSEQ / 128, Bsz * 8), 256, aSmem>>>(q, kv, src_mask, upd);

    // 4) out = [tgt | upd] @ Wo^T + bo  (fused K=2048) -> f32
    gemm_h<<<dim3(1024 / 128, M / 128), 128, gSmem>>>(
        htgt, upd, hwo, 2048, bo, nullptr, out, 1024, 64, 0);
}

// round 15
// speedup vs baseline: 1.0421x; 1.0076x over previous
#include <cuda_runtime.h>
#include <cuda_fp16.h>
#include <cstdint>

#define Bsz 8
#define NSEQ 1024
#define OUTD 1024
#define DHD 128

#define DINLINE __device__ __forceinline__

// ---------------- scratch (allocation-free rule: __device__ globals) ----------
__device__ __align__(16) __half h_kv [8u*1024u*2048u];   // src_trans half [B*NS,2048]
__device__ __align__(16) __half h_q  [8u*1024u*1024u];   // tgt_trans half
__device__ __align__(16) __half h_upd[8u*1024u*1024u];   // tgt_update half
__device__ __align__(16) __half h_src[8u*1024u*1024u];   // fp16 inputs
__device__ __align__(16) __half h_tgt[8u*1024u*1024u];
__device__ __align__(16) __half h_ws [2u*1024u*1024u];
__device__ __align__(16) __half h_wt [1024u*1024u];
__device__ __align__(16) __half h_wo [2u*1024u*1024u];

// ---------------- helpers ------------------------------------------------------
DINLINE uint32_t smem_u32(const void* p) {
    uint32_t a;
    asm("{ .reg .u64 t; cvta.to.shared.u64 t, %1; cvt.u32.u64 %0, t; }" : "=r"(a) : "l"(p));
    return a;
}
DINLINE void cp16(uint32_t dst, const void* src) {
    asm volatile("cp.async.cg.shared.global [%0], [%1], 16;" :: "r"(dst), "l"(src) : "memory");
}
DINLINE void cp_commit() { asm volatile("cp.async.commit_group;" ::: "memory"); }
DINLINE void cp_wait0()  { asm volatile("cp.async.wait_group 0;" ::: "memory"); }
DINLINE void cp_wait1()  { asm volatile("cp.async.wait_group 1;" ::: "memory"); }
DINLINE void cp_wait2()  { asm volatile("cp.async.wait_group 2;" ::: "memory"); }

DINLINE void mma_h(float c[4], const uint32_t a[4], const uint32_t b[2]) {
    asm volatile(
        "mma.sync.aligned.m16n8k16.row.col.f32.f16.f16.f32 "
        "{%0,%1,%2,%3}, {%4,%5,%6,%7}, {%8,%9}, {%0,%1,%2,%3};"
        : "+f"(c[0]), "+f"(c[1]), "+f"(c[2]), "+f"(c[3])
        : "r"(a[0]), "r"(a[1]), "r"(a[2]), "r"(a[3]), "r"(b[0]), "r"(b[1]));
}

DINLINE void ldsm_x4(uint32_t& r0, uint32_t& r1, uint32_t& r2, uint32_t& r3, uint32_t a) {
    asm volatile("ldmatrix.sync.aligned.m8n8.x4.shared.b16 {%0,%1,%2,%3}, [%4];"
                 : "=r"(r0), "=r"(r1), "=r"(r2), "=r"(r3) : "r"(a));
}
DINLINE void ldsm_x4_t(uint32_t& r0, uint32_t& r1, uint32_t& r2, uint32_t& r3, uint32_t a) {
    asm volatile("ldmatrix.sync.aligned.m8n8.x4.trans.shared.b16 {%0,%1,%2,%3}, [%4];"
                 : "=r"(r0), "=r"(r1), "=r"(r2), "=r"(r3) : "r"(a));
}

DINLINE uint32_t ldh2(const __half* p) { return *(const uint32_t*)p; }
DINLINE uint32_t packh2(float x, float y) {
    __half2 h = __floats2half2_rn(x, y);
    return *reinterpret_cast<uint32_t*>(&h);
}

// ================================================================================
// single-launch f32 -> fp16 conversion for all 5 tensors (segmented linear index)
// ================================================================================
DINLINE void cvt8(const float4* in, uint4* out, int i) {
    float4 a = in[2 * i], b = in[2 * i + 1];
    uint4 o;
    o.x = packh2(a.x, a.y);
    o.y = packh2(a.z, a.w);
    o.z = packh2(b.x, b.y);
    o.w = packh2(b.z, b.w);
    out[i] = o;
}

__global__ void f2h_all(const float4* __restrict__ i0, uint4* __restrict__ o0, int n0,
                        const float4* __restrict__ i1, uint4* __restrict__ o1, int n1,
                        const float4* __restrict__ i2, uint4* __restrict__ o2, int n2,
                        const float4* __restrict__ i3, uint4* __restrict__ o3, int n3,
                        const float4* __restrict__ i4, uint4* __restrict__ o4, int n4)
{
    int i = blockIdx.x * blockDim.x + threadIdx.x;
    if (i < n0) { cvt8(i0, o0, i); return; }
    i -= n0;
    if (i < n1) { cvt8(i1, o1, i); return; }
    i -= n1;
    if (i < n2) { cvt8(i2, o2, i); return; }
    i -= n2;
    if (i < n3) { cvt8(i3, o3, i); return; }
    i -= n3;
    if (i < n4) { cvt8(i4, o4, i); }
}

// ================================================================================
// fp16 GEMM body (R10-proven): BM=BN=128, BK=32, 4 warps 64x64, ldmatrix.x4,
// 4-stage cp.async, single __syncthreads per k-block. outHalf: 1=fp16, 0=f32.
// ================================================================================
#define GS 4
#define STGH (2 * 128 * 40)
#define STGB (STGH * 2)

DINLINE void gemm_body(const __half* __restrict__ A0, const __half* __restrict__ A1,
                       const __half* __restrict__ W, int ldw,
                       const float* __restrict__ bias, const float* __restrict__ rowmask,
                       void* __restrict__ Cv, int ldc, int nkb, int outHalf,
                       int mBase, int nBase, __half* smh)
{
    const uint32_t sb = smem_u32(smh);

    const int tid  = threadIdx.x;
    const int lane = tid & 31;
    const int wid  = tid >> 5;
    const int wm   = wid & 1;
    const int wn   = wid >> 1;
    const int g    = lane >> 2;
    const int tg   = lane & 3;

    uint32_t dOf[4];
    int aOf[4], wOf[4];
#pragma unroll
    for (int i = 0; i < 4; i++) {
        int idx = tid + i * 128;
        int row = idx >> 2, c = idx & 3;
        dOf[i] = row * 80 + c * 16;
        aOf[i] = (mBase + row) * 1024 + c * 8;
        wOf[i] = (nBase + row) * ldw + c * 8;
    }

    auto ISSUE = [&](int kb) {
        const int s = kb & 3;
        const int kg = kb * 32;
        const __half* Ap = (kg < 1024) ? A0 : A1;
        const int ka = kg & 1023;
        const uint32_t sa  = sb + s * STGB;
        const uint32_t sbb = sa + 128 * 80;
#pragma unroll
        for (int i = 0; i < 4; i++) cp16(sa  + dOf[i], Ap + aOf[i] + ka);
#pragma unroll
        for (int i = 0; i < 4; i++) cp16(sbb + dOf[i], W  + wOf[i] + kg);
        cp_commit();
    };

    const uint32_t aLn = (lane & 15) * 80 + ((lane & 16) ? 16u : 0u);
    const uint32_t bLn = (lane & 7) * 80 + ((lane & 16) ? 8u * 80u : 0u) + ((lane & 8) ? 16u : 0u);

    float acc[4][8][4];
#pragma unroll
    for (int mt = 0; mt < 4; mt++)
#pragma unroll
        for (int nt = 0; nt < 8; nt++)
#pragma unroll
            for (int i = 0; i < 4; i++) acc[mt][nt][i] = 0.f;

    ISSUE(0); ISSUE(1); ISSUE(2);

    for (int kb = 0; kb < nkb; kb++) {
        if (kb < nkb - 2)      cp_wait2();
        else if (kb < nkb - 1) cp_wait1();
        else                   cp_wait0();
        __syncthreads();
        if (kb + 3 < nkb) ISSUE(kb + 3);

        const uint32_t saA = sb + (kb & 3) * STGB;
        const uint32_t saB = saA + 128 * 80;
#pragma unroll
        for (int ks = 0; ks < 2; ks++) {
            const uint32_t aBase = saA + (uint32_t)(wm * 64) * 80 + ks * 32 + aLn;
            const uint32_t bBase = saB + (uint32_t)(wn * 64) * 80 + ks * 32 + bLn;
            uint32_t af[4][4], bf[8][2];
#pragma unroll
            for (int mt = 0; mt < 4; mt++)
                ldsm_x4(af[mt][0], af[mt][1], af[mt][2], af[mt][3], aBase + mt * 16 * 80);
#pragma unroll
            for (int p = 0; p < 4; p++)
                ldsm_x4(bf[2*p][0], bf[2*p][1], bf[2*p+1][0], bf[2*p+1][1], bBase + p * 16 * 80);
#pragma unroll
            for (int mt = 0; mt < 4; mt++)
#pragma unroll
                for (int nt = 0; nt < 8; nt++)
                    mma_h(acc[mt][nt], af[mt], bf[nt]);
        }
    }

#pragma unroll
    for (int mt = 0; mt < 4; mt++) {
        int r0 = mBase + wm * 64 + mt * 16 + g;
        float mk0 = rowmask ? rowmask[r0]     : 1.f;
        float mk1 = rowmask ? rowmask[r0 + 8] : 1.f;
#pragma unroll
        for (int nt = 0; nt < 8; nt++) {
            int c = nBase + wn * 64 + nt * 8 + 2 * tg;
            float b0 = bias ? bias[c]     : 0.f;
            float b1 = bias ? bias[c + 1] : 0.f;
            float v00 = (acc[mt][nt][0] + b0) * mk0;
            float v01 = (acc[mt][nt][1] + b1) * mk0;
            float v10 = (acc[mt][nt][2] + b0) * mk1;
            float v11 = (acc[mt][nt][3] + b1) * mk1;
            if (outHalf) {
                __half* Ch = (__half*)Cv;
                *(uint32_t*)(Ch + (size_t)r0 * ldc + c)       = packh2(v00, v01);
                *(uint32_t*)(Ch + (size_t)(r0 + 8) * ldc + c) = packh2(v10, v11);
            } else {
                float* Cf = (float*)Cv;
                *(float2*)(Cf + (size_t)r0 * ldc + c)       = make_float2(v00, v01);
                *(float2*)(Cf + (size_t)(r0 + 8) * ldc + c) = make_float2(v10, v11);
            }
        }
    }
}

// out-GEMM (fused K=2048 concat)
__global__ __launch_bounds__(128, 2)
void gemm_h(const __half* __restrict__ A0, const __half* __restrict__ A1,
            const __half* __restrict__ W, int ldw,
            const float* __restrict__ bias, const float* __restrict__ rowmask,
            void* __restrict__ Cv, int ldc, int nkb, int outHalf)
{
    extern __shared__ __half smh[];
    gemm_body(A0, A1, W, ldw, bias, rowmask, Cv, ldc, nkb, outHalf,
              blockIdx.y * 128, blockIdx.x * 128, smh);
}

// merged projection GEMMs: x<16 -> kv (N=2048), x>=16 -> q (N=1024)
__global__ __launch_bounds__(128, 2)
void gemm12_h(const __half* __restrict__ Asrc, const __half* __restrict__ Ws_,
              const float* __restrict__ bs_, const float* __restrict__ smask,
              __half* __restrict__ kv,
              const __half* __restrict__ Atgt, const __half* __restrict__ Wt_,
              const float* __restrict__ bt_, const float* __restrict__ tmask,
              __half* __restrict__ q)
{
    extern __shared__ __half smh[];
    if (blockIdx.x < 16)
        gemm_body(Asrc, Asrc, Ws_, 1024, bs_, smask, kv, 2048, 32, 1,
                  blockIdx.y * 128, blockIdx.x * 128, smh);
    else
        gemm_body(Atgt, Atgt, Wt_, 1024, bt_, tmask, q, 1024, 32, 1,
                  blockIdx.y * 128, (blockIdx.x - 16) * 128, smh);
}

// ================================================================================
// fp16 flash attention v5: BM=64, 128 threads (4 warps x 16 rows), 2 CTAs/SM,
// 256-reg headroom (was capped at 128). Per-warp fragment mappings IDENTICAL to
// the proven R12 kernel. P in regs, Q in smem via ldmatrix, exp2 softmax.
// smem (halves): Q[64][136] | K[2][64][136] | V[2][64][136] | f32 mask[2][64]
// ================================================================================
#define QH  (64 * 136)
#define KST (64 * 136)
#define VST (64 * 136)
#define KOFF QH
#define VOFF (QH + 2 * KST)
#define MBYTE ((VOFF + 2 * VST) * 2)
#define ATTN_SMEMB (MBYTE + 2 * 64 * 4)

__global__ __launch_bounds__(128, 2)
void attn_h(const __half* __restrict__ Q, const __half* __restrict__ KV,
            const float* __restrict__ smask, __half* __restrict__ O)
{
    extern __shared__ __half smh[];
    const uint32_t sb = smem_u32(smh);

    const int tid  = threadIdx.x;
    const int lane = tid & 31;
    const int w    = tid >> 5;       // 0..3 -> rows w*16 .. w*16+15
    const int g    = lane >> 2;
    const int tg   = lane & 3;

    const int bh = blockIdx.y;
    const int b  = bh >> 3;
    const int hh = bh & 7;
    const int t0 = blockIdx.x * 64;

    const __half* qg = Q + ((size_t)b * NSEQ + t0) * OUTD + hh * DHD;
    const __half* kg = KV + (size_t)b * NSEQ * (2 * OUTD) + hh * DHD;
    const __half* vg = kg + OUTD;
    const float*  mg = smask + (size_t)b * NSEQ;

    // ---- load Q (64 x 128 halves) into dedicated smem via cp.async ----
#pragma unroll
    for (int i = 0; i < 8; i++) {
        int idx = tid + i * 128;
        int row = idx >> 4, c8 = idx & 15;
        cp16(sb + (row * 136 + c8 * 8) * 2, qg + (size_t)row * OUTD + c8 * 8);
    }
    cp_commit();

    auto ISSUE = [&](int j) {
        const int st = j & 1;
#pragma unroll
        for (int i = 0; i < 8; i++) {
            int idx = tid + i * 128;
            int row = idx >> 4, c = idx & 15;
            size_t go = (size_t)(j * 64 + row) * (2 * OUTD) + c * 8;
            cp16(sb + (KOFF + st * KST + row * 136 + c * 8) * 2, kg + go);
            cp16(sb + (VOFF + st * VST + row * 136 + c * 8) * 2, vg + go);
        }
        if (tid < 16)
            cp16(sb + MBYTE + st * 256 + tid * 16, mg + j * 64 + tid * 4);
        cp_commit();
    };

    float oacc[16][4];
#pragma unroll
    for (int nt = 0; nt < 16; nt++)
#pragma unroll
        for (int i = 0; i < 4; i++) oacc[nt][i] = 0.f;
    float m0 = -1e30f, m1 = -1e30f, l0 = 0.f, l1 = 0.f;

    const float sc2 = 0.12756277212531545f;  // (1/sqrt(128)) * log2(e)
    const int vlane = (lane & 15) * 136 + ((lane & 16) ? 8 : 0);
    const uint32_t kLn = (lane & 7) * 272 + ((lane & 16) ? 8u * 272u : 0u) + ((lane & 8) ? 16u : 0u);
    const uint32_t qLn = (lane & 15) * 272 + ((lane & 16) ? 16u : 0u);
    const uint32_t qbase = sb + (uint32_t)(w * 16) * 272;

    ISSUE(0);

    for (int j = 0; j < NSEQ / 64; j++) {
        const int st = j & 1;
        cp_wait0();
        __syncthreads();
        if (j + 1 < NSEQ / 64) ISSUE(j + 1);

        const float*  msk = (const float*)((const char*)smh + MBYTE + st * 256);
        const uint32_t kbase = sb + (KOFF + st * KST) * 2;
        const uint32_t vbase = sb + (VOFF + st * VST) * 2;

        // S = Q @ K^T
        float sacc[8][4];
#pragma unroll
        for (int nt = 0; nt < 8; nt++)
#pragma unroll
            for (int i = 0; i < 4; i++) sacc[nt][i] = 0.f;

#pragma unroll
        for (int ks = 0; ks < 8; ks++) {
            uint32_t qa[4];
            ldsm_x4(qa[0], qa[1], qa[2], qa[3], qbase + ks * 32 + qLn);
            const uint32_t bBase = kbase + ks * 32 + kLn;
            uint32_t bf[8][2];
#pragma unroll
            for (int p = 0; p < 4; p++)
                ldsm_x4(bf[2*p][0], bf[2*p][1], bf[2*p+1][0], bf[2*p+1][1], bBase + p * 16 * 272);
#pragma unroll
            for (int nt = 0; nt < 8; nt++)
                mma_h(sacc[nt], qa, bf[nt]);
        }

        // scale (log2 domain) + mask + row max
        float rmax0 = -1e30f, rmax1 = -1e30f;
#pragma unroll
        for (int nt = 0; nt < 8; nt++) {
#pragma unroll
            for (int i = 0; i < 4; i++) {
                float sv = sacc[nt][i] * sc2;
                int col = nt * 8 + 2 * tg + (i & 1);
                if (msk[col] == 0.f) sv = -1e30f;
                sacc[nt][i] = sv;
                if (i < 2) rmax0 = fmaxf(rmax0, sv);
                else       rmax1 = fmaxf(rmax1, sv);
            }
        }
        rmax0 = fmaxf(rmax0, __shfl_xor_sync(0xffffffffu, rmax0, 1));
        rmax0 = fmaxf(rmax0, __shfl_xor_sync(0xffffffffu, rmax0, 2));
        rmax1 = fmaxf(rmax1, __shfl_xor_sync(0xffffffffu, rmax1, 1));
        rmax1 = fmaxf(rmax1, __shfl_xor_sync(0xffffffffu, rmax1, 2));

        float mn0 = fmaxf(m0, rmax0), mn1 = fmaxf(m1, rmax1);
        float cf0 = exp2f(m0 - mn0), cf1 = exp2f(m1 - mn1);
        m0 = mn0; m1 = mn1;

        // P = 2^(S2 - m2), packed straight into A-fragments
        uint32_t pp[8][2];
        float rs0 = 0.f, rs1 = 0.f;
#pragma unroll
        for (int nt = 0; nt < 8; nt++) {
            float p0 = exp2f(sacc[nt][0] - mn0);
            float p1 = exp2f(sacc[nt][1] - mn0);
            float p2 = exp2f(sacc[nt][2] - mn1);
            float p3 = exp2f(sacc[nt][3] - mn1);
            rs0 += p0 + p1; rs1 += p2 + p3;
            pp[nt][0] = packh2(p0, p1);
            pp[nt][1] = packh2(p2, p3);
        }
        rs0 += __shfl_xor_sync(0xffffffffu, rs0, 1);
        rs0 += __shfl_xor_sync(0xffffffffu, rs0, 2);
        rs1 += __shfl_xor_sync(0xffffffffu, rs1, 1);
        rs1 += __shfl_xor_sync(0xffffffffu, rs1, 2);
        l0 = l0 * cf0 + rs0;
        l1 = l1 * cf1 + rs1;

#pragma unroll
        for (int nt = 0; nt < 16; nt++) {
            oacc[nt][0] *= cf0; oacc[nt][1] *= cf0;
            oacc[nt][2] *= cf1; oacc[nt][3] *= cf1;
        }

        // O += P @ V
#pragma unroll
        for (int ks = 0; ks < 4; ks++) {
            uint32_t pa[4];
            pa[0] = pp[2 * ks][0];
            pa[1] = pp[2 * ks][1];
            pa[2] = pp[2 * ks + 1][0];
            pa[3] = pp[2 * ks + 1][1];
            const uint32_t vrow = vbase + (ks * 16 * 136 + vlane) * 2;
#pragma unroll
            for (int dg = 0; dg < 8; dg++) {
                uint32_t r0, r1, r2, r3;
                ldsm_x4_t(r0, r1, r2, r3, vrow + dg * 32);
                uint32_t b0[2] = {r0, r1}, b1[2] = {r2, r3};
                mma_h(oacc[2 * dg],     pa, b0);
                mma_h(oacc[2 * dg + 1], pa, b1);
            }
        }
    }

    float inv0 = 1.f / l0, inv1 = 1.f / l1;
    const int tr0 = t0 + w * 16 + g;
    __half* og = O + (size_t)b * NSEQ * OUTD + hh * DHD;
#pragma unroll
    for (int nt = 0; nt < 16; nt++) {
        int dc = nt * 8 + 2 * tg;
        *(uint32_t*)(og + (size_t)tr0 * OUTD + dc) =
            packh2(oacc[nt][0] * inv0, oacc[nt][1] * inv0);
        *(uint32_t*)(og + (size_t)(tr0 + 8) * OUTD + dc) =
            packh2(oacc[nt][2] * inv1, oacc[nt][3] * inv1);
    }
}

// ================================================================================
// launch
// ================================================================================
extern "C" void kernel_launch(void* const* d_in, const int* in_sizes, int n_in,
                              void* d_out, int out_size)
{
    const float* src      = (const float*)d_in[0];
    const float* tgt      = (const float*)d_in[1];
    const float* src_mask = (const float*)d_in[2];
    const float* tgt_mask = (const float*)d_in[3];
    const float* Ws       = (const float*)d_in[4];
    const float* bs       = (const float*)d_in[5];
    const float* Wt       = (const float*)d_in[6];
    const float* bt       = (const float*)d_in[7];
    const float* Wo       = (const float*)d_in[8];
    const float* bo       = (const float*)d_in[9];
    float* out = (float*)d_out;

    __half *kv, *q, *upd, *hsrc, *htgt, *hws, *hwt, *hwo;
    cudaGetSymbolAddress((void**)&kv,   h_kv);
    cudaGetSymbolAddress((void**)&q,    h_q);
    cudaGetSymbolAddress((void**)&upd,  h_upd);
    cudaGetSymbolAddress((void**)&hsrc, h_src);
    cudaGetSymbolAddress((void**)&htgt, h_tgt);
    cudaGetSymbolAddress((void**)&hws,  h_ws);
    cudaGetSymbolAddress((void**)&hwt,  h_wt);
    cudaGetSymbolAddress((void**)&hwo,  h_wo);

    const int gSmem = GS * STGB;               // 81920
    const int aSmem = ATTN_SMEMB;              // ~88KB
    cudaFuncSetAttribute(gemm_h,   cudaFuncAttributeMaxDynamicSharedMemorySize, gSmem);
    cudaFuncSetAttribute(gemm12_h, cudaFuncAttributeMaxDynamicSharedMemorySize, gSmem);
    cudaFuncSetAttribute(attn_h,   cudaFuncAttributeMaxDynamicSharedMemorySize, aSmem);

    // 0) single-launch f32 -> fp16 conversion of all inputs
    const int nSrc = 8*1024*1024/8, nW2 = 2*1024*1024/8, nW1 = 1024*1024/8;
    const int nTot = 2 * nSrc + 2 * nW2 + nW1;
    f2h_all<<<(nTot + 255) / 256, 256>>>(
        (const float4*)src, (uint4*)hsrc, nSrc,
        (const float4*)tgt, (uint4*)htgt, nSrc,
        (const float4*)Ws,  (uint4*)hws,  nW2,
        (const float4*)Wt,  (uint4*)hwt,  nW1,
        (const float4*)Wo,  (uint4*)hwo,  nW2);

    const int M = Bsz * NSEQ; // 8192

    // 1+2) merged: kv = src@Ws^T+bs (*src_mask), q = tgt@Wt^T+bt (*tgt_mask)
    gemm12_h<<<dim3(24, M / 128), 128, gSmem>>>(
        hsrc, hws, bs, src_mask, kv,
        htgt, hwt, bt, tgt_mask, q);

    // 3) flash attention -> upd fp16       [8192, 1024]
    attn_h<<<dim3(NSEQ / 64, Bsz * 8), 128, aSmem>>>(q, kv, src_mask, upd);

    // 4) out = [tgt | upd] @ Wo^T + bo  (fused K=2048) -> f32
    gemm_h<<<dim3(1024 / 128, M / 128), 128, gSmem>>>(
        htgt, upd, hwo, 2048, bo, nullptr, out, 1024, 64, 0);
}